// round 1
// baseline (speedup 1.0000x reference)
#include <cuda_runtime.h>
#include <math.h>

#define BATCH 4096
#define HID   1024
#define NOUT  4096   // 4*H

// Scratch for pre-activation gates (graph-capture safe: static device global)
__device__ float g_ifgo[(size_t)BATCH * NOUT];

// ---------------------------------------------------------------------------
// Kernel 1: ifgo = h @ W_h + x @ W_x + b_h
// Classic 128x128 tile SGEMM, 8x8 per thread, 256 threads, BK=16.
// Two K-passes (h/W_h then x/W_x) sharing accumulators.
// ---------------------------------------------------------------------------
#define BM 128
#define BN 128
#define BK 16
#define TM 8
#define TN 8

__global__ __launch_bounds__(256, 2) void gemm_ifgo_kernel(
    const float* __restrict__ h, const float* __restrict__ x,
    const float* __restrict__ W_h, const float* __restrict__ W_x,
    const float* __restrict__ b_h)
{
    __shared__ float As[BK][BM + 1];   // +1 pad: kill store bank conflicts
    __shared__ float Bs[BK][BN];

    const int block_row = blockIdx.y * BM;
    const int block_col = blockIdx.x * BN;

    const int tid  = threadIdx.x;
    const int tRow = tid / 16;          // 0..15
    const int tCol = tid % 16;          // 0..15

    // A-tile loader: 128 rows x 16 k, float4 along k. 2 loads/thread.
    const int a_row = tid / 4;          // 0..63
    const int a_col = (tid % 4) * 4;    // 0,4,8,12
    // B-tile loader: 16 k x 128 n, float4 along n. 2 loads/thread.
    const int b_row = tid / 32;         // 0..7
    const int b_col = (tid % 32) * 4;   // 0..124

    float acc[TM][TN];
    #pragma unroll
    for (int i = 0; i < TM; ++i)
        #pragma unroll
        for (int j = 0; j < TN; ++j) acc[i][j] = 0.f;

    #pragma unroll 1
    for (int pass = 0; pass < 2; ++pass) {
        const float* __restrict__ A = (pass == 0) ? h   : x;
        const float* __restrict__ W = (pass == 0) ? W_h : W_x;

        #pragma unroll 1
        for (int k0 = 0; k0 < HID; k0 += BK) {
            #pragma unroll
            for (int i = 0; i < 2; ++i) {
                int m = a_row + i * 64;
                float4 v = *(const float4*)&A[(size_t)(block_row + m) * HID + k0 + a_col];
                As[a_col + 0][m] = v.x;
                As[a_col + 1][m] = v.y;
                As[a_col + 2][m] = v.z;
                As[a_col + 3][m] = v.w;
            }
            #pragma unroll
            for (int i = 0; i < 2; ++i) {
                int kk = b_row + i * 8;
                *(float4*)&Bs[kk][b_col] =
                    *(const float4*)&W[(size_t)(k0 + kk) * NOUT + block_col + b_col];
            }
            __syncthreads();

            #pragma unroll
            for (int k = 0; k < BK; ++k) {
                float regM[TM], regN[TN];
                #pragma unroll
                for (int i = 0; i < TM; ++i) regM[i] = As[k][tRow * TM + i];
                float4 n0 = *(const float4*)&Bs[k][tCol * TN];
                float4 n1 = *(const float4*)&Bs[k][tCol * TN + 4];
                regN[0] = n0.x; regN[1] = n0.y; regN[2] = n0.z; regN[3] = n0.w;
                regN[4] = n1.x; regN[5] = n1.y; regN[6] = n1.z; regN[7] = n1.w;
                #pragma unroll
                for (int i = 0; i < TM; ++i)
                    #pragma unroll
                    for (int j = 0; j < TN; ++j)
                        acc[i][j] = fmaf(regM[i], regN[j], acc[i][j]);
            }
            __syncthreads();
        }
    }

    // Epilogue: add bias, store to scratch
    #pragma unroll
    for (int i = 0; i < TM; ++i) {
        int row = block_row + tRow * TM + i;
        #pragma unroll
        for (int j = 0; j < TN; j += 4) {
            int col = block_col + tCol * TN + j;
            float4 bv = *(const float4*)&b_h[col];
            float4 v;
            v.x = acc[i][j + 0] + bv.x;
            v.y = acc[i][j + 1] + bv.y;
            v.z = acc[i][j + 2] + bv.z;
            v.w = acc[i][j + 3] + bv.w;
            *(float4*)&g_ifgo[(size_t)row * NOUT + col] = v;
        }
    }
}

// ---------------------------------------------------------------------------
// Kernel 2: per-row LayerNorm(4 gates) + LSTM pointwise + LayerNorm(c_next)
// One block (256 threads) per batch row.
// ---------------------------------------------------------------------------
__device__ __forceinline__ void warpReduce2(float& a, float& b) {
    #pragma unroll
    for (int o = 16; o > 0; o >>= 1) {
        a += __shfl_down_sync(0xffffffffu, a, o);
        b += __shfl_down_sync(0xffffffffu, b, o);
    }
}

__device__ __forceinline__ float sigmoidf_(float v) {
    return 1.0f / (1.0f + expf(-v));
}

__global__ __launch_bounds__(256) void ln_lstm_kernel(
    const float* __restrict__ c,
    const float* __restrict__ ln_g, const float* __restrict__ ln_b,
    const float* __restrict__ lnc_g, const float* __restrict__ lnc_b,
    float* __restrict__ h_next, float* __restrict__ c_next_out)
{
    const int b   = blockIdx.x;
    const int tid = threadIdx.x;
    const int lane = tid & 31, warp = tid >> 5;
    const float* __restrict__ row = &g_ifgo[(size_t)b * NOUT];

    __shared__ float s_wa[8], s_wb[8];
    __shared__ float s_mean[4], s_rstd[4];
    __shared__ float s_c[HID];
    __shared__ float s_o[HID];
    __shared__ float s_cmu, s_crstd;

    // --- stats for the 4 gates ---
    #pragma unroll 1
    for (int g = 0; g < 4; ++g) {
        float sum = 0.f, sq = 0.f;
        #pragma unroll
        for (int j = tid; j < HID; j += 256) {
            float v = row[g * HID + j];
            sum += v; sq += v * v;
        }
        warpReduce2(sum, sq);
        if (lane == 0) { s_wa[warp] = sum; s_wb[warp] = sq; }
        __syncthreads();
        if (warp == 0) {
            float a2 = (lane < 8) ? s_wa[lane] : 0.f;
            float b2 = (lane < 8) ? s_wb[lane] : 0.f;
            warpReduce2(a2, b2);
            if (lane == 0) {
                float mu  = a2 * (1.0f / HID);
                float var = b2 * (1.0f / HID) - mu * mu;
                s_mean[g] = mu;
                s_rstd[g] = rsqrtf(var + 1e-5f);
            }
        }
        __syncthreads();
    }

    const float mu_i = s_mean[0], rs_i = s_rstd[0];
    const float mu_f = s_mean[1], rs_f = s_rstd[1];
    const float mu_g = s_mean[2], rs_g = s_rstd[2];
    const float mu_o = s_mean[3], rs_o = s_rstd[3];

    // --- LSTM pointwise + collect c_next stats ---
    float csum = 0.f, csq = 0.f;
    #pragma unroll
    for (int j = tid; j < HID; j += 256) {
        float iv = (row[0 * HID + j] - mu_i) * rs_i * ln_g[0 * HID + j] + ln_b[0 * HID + j];
        float fv = (row[1 * HID + j] - mu_f) * rs_f * ln_g[1 * HID + j] + ln_b[1 * HID + j];
        float gv = (row[2 * HID + j] - mu_g) * rs_g * ln_g[2 * HID + j] + ln_b[2 * HID + j];
        float ov = (row[3 * HID + j] - mu_o) * rs_o * ln_g[3 * HID + j] + ln_b[3 * HID + j];

        float cn = sigmoidf_(fv) * c[(size_t)b * HID + j] + sigmoidf_(iv) * tanhf(gv);
        s_c[j] = cn;
        s_o[j] = ov;
        c_next_out[(size_t)b * HID + j] = cn;
        csum += cn; csq += cn * cn;
    }

    warpReduce2(csum, csq);
    if (lane == 0) { s_wa[warp] = csum; s_wb[warp] = csq; }
    __syncthreads();
    if (warp == 0) {
        float a2 = (lane < 8) ? s_wa[lane] : 0.f;
        float b2 = (lane < 8) ? s_wb[lane] : 0.f;
        warpReduce2(a2, b2);
        if (lane == 0) {
            float mu  = a2 * (1.0f / HID);
            float var = b2 * (1.0f / HID) - mu * mu;
            s_cmu = mu;
            s_crstd = rsqrtf(var + 1e-5f);
        }
    }
    __syncthreads();

    const float cmu = s_cmu, crstd = s_crstd;
    #pragma unroll
    for (int j = tid; j < HID; j += 256) {
        float lnc = (s_c[j] - cmu) * crstd * lnc_g[j] + lnc_b[j];
        h_next[(size_t)b * HID + j] = sigmoidf_(s_o[j]) * tanhf(lnc);
    }
}

// ---------------------------------------------------------------------------
extern "C" void kernel_launch(void* const* d_in, const int* in_sizes, int n_in,
                              void* d_out, int out_size)
{
    const float* x     = (const float*)d_in[0];
    const float* h     = (const float*)d_in[1];
    const float* c     = (const float*)d_in[2];
    const float* W_h   = (const float*)d_in[3];
    const float* b_h   = (const float*)d_in[4];
    const float* W_x   = (const float*)d_in[5];
    const float* ln_g  = (const float*)d_in[6];
    const float* ln_b  = (const float*)d_in[7];
    const float* lnc_g = (const float*)d_in[8];
    const float* lnc_b = (const float*)d_in[9];

    float* out    = (float*)d_out;
    float* h_next = out;
    float* c_next = out + (size_t)BATCH * HID;

    dim3 grid(NOUT / BN, BATCH / BM);
    gemm_ifgo_kernel<<<grid, 256>>>(h, x, W_h, W_x, b_h);
    ln_lstm_kernel<<<BATCH, 256>>>(c, ln_g, ln_b, lnc_g, lnc_b, h_next, c_next);
}

// round 2
// speedup vs baseline: 2.1602x; 2.1602x over previous
#include <cuda_runtime.h>
#include <math.h>
#include <stdint.h>

#define BATCH 4096
#define HID   1024
#define NOUT  4096   // 4*H

// Scratch (graph-capture safe static device globals)
__device__ float g_ifgo[(size_t)BATCH * NOUT];
__device__ float g_hr [(size_t)BATCH * HID];
__device__ float g_xr [(size_t)BATCH * HID];
__device__ float g_Whr[(size_t)HID * NOUT];
__device__ float g_Wxr[(size_t)HID * NOUT];

// ---------------------------------------------------------------------------
// Pre-round all GEMM operands to tf32 (RNA) to avoid truncation bias and
// avoid per-fragment cvt in the GEMM mainloop. All 4 arrays are 4M floats.
// ---------------------------------------------------------------------------
__global__ void cvt_tf32_kernel(const float* __restrict__ s0, float* __restrict__ d0,
                                const float* __restrict__ s1, float* __restrict__ d1,
                                const float* __restrict__ s2, float* __restrict__ d2,
                                const float* __restrict__ s3, float* __restrict__ d3,
                                int n)
{
    int stride = gridDim.x * blockDim.x;
    for (int i = blockIdx.x * blockDim.x + threadIdx.x; i < n; i += stride) {
        uint32_t u;
        asm("cvt.rna.tf32.f32 %0, %1;" : "=r"(u) : "f"(s0[i])); d0[i] = __uint_as_float(u);
        asm("cvt.rna.tf32.f32 %0, %1;" : "=r"(u) : "f"(s1[i])); d1[i] = __uint_as_float(u);
        asm("cvt.rna.tf32.f32 %0, %1;" : "=r"(u) : "f"(s2[i])); d2[i] = __uint_as_float(u);
        asm("cvt.rna.tf32.f32 %0, %1;" : "=r"(u) : "f"(s3[i])); d3[i] = __uint_as_float(u);
    }
}

// ---------------------------------------------------------------------------
// tf32 tensor-core GEMM: ifgo = h @ W_h + x @ W_x + b_h
// 128x128 block tile, 4 warps (64x64 each), BK=16, m16n8k8 tf32 mma,
// double-buffered smem via cp.async.cg.
// ---------------------------------------------------------------------------
#define BM 128
#define BN 128
#define BK 16
#define ASTR 20    // As row stride (floats): banks 20q+c conflict-free
#define BSTR 136   // Bs row stride (floats): banks 8c+q  conflict-free
#define NKTILES 128  // 2 passes * (1024/16)

__device__ __forceinline__ void cpa16(uint32_t dst, const float* src) {
    asm volatile("cp.async.cg.shared.global [%0], [%1], 16;\n" :: "r"(dst), "l"(src));
}
__device__ __forceinline__ void cpa_commit() {
    asm volatile("cp.async.commit_group;\n" ::: "memory");
}
__device__ __forceinline__ void cpa_wait0() {
    asm volatile("cp.async.wait_group 0;\n" ::: "memory");
}

__global__ __launch_bounds__(128) void gemm_tf32_kernel(const float* __restrict__ b_h)
{
    __shared__ float As[2][BM * ASTR];   // 2 x 10240 B
    __shared__ float Bs[2][BK * BSTR];   // 2 x  8704 B

    const int tid  = threadIdx.x;
    const int lane = tid & 31;
    const int wid  = tid >> 5;         // 0..3
    const int wm   = wid >> 1;         // warp row 0..1  -> 64 rows
    const int wn   = wid & 1;          // warp col 0..1  -> 64 cols
    const int qid  = lane >> 2;        // 0..7
    const int cid  = lane & 3;         // 0..3

    const int brow = blockIdx.y * BM;
    const int bcol = blockIdx.x * BN;

    const float* Aops[2] = { g_hr, g_xr };
    const float* Wops[2] = { g_Whr, g_Wxr };

    // staging assignment
    const int a_m  = tid;                 // A: one row per thread, 4 x 16B
    const int b_k  = tid >> 3;            // B: k row 0..15
    const int b_n  = (tid & 7) * 16;      // 8 threads x 64 floats per k row

    uint32_t as_base[2], bs_base[2];
    as_base[0] = (uint32_t)__cvta_generic_to_shared(&As[0][0]);
    as_base[1] = (uint32_t)__cvta_generic_to_shared(&As[1][0]);
    bs_base[0] = (uint32_t)__cvta_generic_to_shared(&Bs[0][0]);
    bs_base[1] = (uint32_t)__cvta_generic_to_shared(&Bs[1][0]);

    auto stage = [&](int tile, int buf) {
        int pass = tile >> 6;
        int kt   = (tile & 63) * BK;
        const float* A = Aops[pass];
        const float* W = Wops[pass];
        const float* asrc = A + (size_t)(brow + a_m) * HID + kt;
        uint32_t adst = as_base[buf] + (uint32_t)(a_m * ASTR) * 4u;
        #pragma unroll
        for (int c = 0; c < 4; ++c) cpa16(adst + c * 16u, asrc + c * 4);
        const float* bsrc = W + (size_t)(kt + b_k) * NOUT + bcol + b_n;
        uint32_t bdst = bs_base[buf] + (uint32_t)(b_k * BSTR + b_n) * 4u;
        #pragma unroll
        for (int c = 0; c < 4; ++c) cpa16(bdst + c * 16u, bsrc + c * 4);
        cpa_commit();
    };

    float acc[4][8][4];
    #pragma unroll
    for (int i = 0; i < 4; ++i)
        #pragma unroll
        for (int j = 0; j < 8; ++j)
            #pragma unroll
            for (int r = 0; r < 4; ++r) acc[i][j][r] = 0.f;

    stage(0, 0);

    #pragma unroll 1
    for (int t = 0; t < NKTILES; ++t) {
        const int buf = t & 1;
        cpa_wait0();
        __syncthreads();
        if (t + 1 < NKTILES) stage(t + 1, buf ^ 1);

        const uint32_t* ap = (const uint32_t*)&As[buf][0];
        const uint32_t* bp = (const uint32_t*)&Bs[buf][0];

        #pragma unroll
        for (int ks = 0; ks < BK; ks += 8) {
            uint32_t af[4][4];
            #pragma unroll
            for (int i = 0; i < 4; ++i) {
                int m = wm * 64 + i * 16 + qid;
                af[i][0] = ap[(m    ) * ASTR + ks + cid    ];
                af[i][1] = ap[(m + 8) * ASTR + ks + cid    ];
                af[i][2] = ap[(m    ) * ASTR + ks + cid + 4];
                af[i][3] = ap[(m + 8) * ASTR + ks + cid + 4];
            }
            #pragma unroll
            for (int j = 0; j < 8; ++j) {
                int n = wn * 64 + j * 8 + qid;
                uint32_t b0 = bp[(ks + cid    ) * BSTR + n];
                uint32_t b1 = bp[(ks + cid + 4) * BSTR + n];
                #pragma unroll
                for (int i = 0; i < 4; ++i) {
                    asm volatile(
                        "mma.sync.aligned.m16n8k8.row.col.f32.tf32.tf32.f32 "
                        "{%0,%1,%2,%3}, {%4,%5,%6,%7}, {%8,%9}, {%0,%1,%2,%3};\n"
                        : "+f"(acc[i][j][0]), "+f"(acc[i][j][1]),
                          "+f"(acc[i][j][2]), "+f"(acc[i][j][3])
                        : "r"(af[i][0]), "r"(af[i][1]), "r"(af[i][2]), "r"(af[i][3]),
                          "r"(b0), "r"(b1));
                }
            }
        }
        __syncthreads();
    }

    // Epilogue: bias + store
    #pragma unroll
    for (int i = 0; i < 4; ++i) {
        int r0 = brow + wm * 64 + i * 16 + qid;
        #pragma unroll
        for (int j = 0; j < 8; ++j) {
            int col = bcol + wn * 64 + j * 8 + 2 * cid;
            float2 bb = *(const float2*)&b_h[col];
            float2 v0 = { acc[i][j][0] + bb.x, acc[i][j][1] + bb.y };
            float2 v1 = { acc[i][j][2] + bb.x, acc[i][j][3] + bb.y };
            *(float2*)&g_ifgo[(size_t)r0       * NOUT + col] = v0;
            *(float2*)&g_ifgo[(size_t)(r0 + 8) * NOUT + col] = v1;
        }
    }
}

// ---------------------------------------------------------------------------
// Kernel 2: per-row LayerNorm(4 gates) + LSTM pointwise + LayerNorm(c_next)
// (unchanged from round 1; 53us, not the bottleneck)
// ---------------------------------------------------------------------------
__device__ __forceinline__ void warpReduce2(float& a, float& b) {
    #pragma unroll
    for (int o = 16; o > 0; o >>= 1) {
        a += __shfl_down_sync(0xffffffffu, a, o);
        b += __shfl_down_sync(0xffffffffu, b, o);
    }
}
__device__ __forceinline__ float sigmoidf_(float v) {
    return 1.0f / (1.0f + expf(-v));
}

__global__ __launch_bounds__(256) void ln_lstm_kernel(
    const float* __restrict__ c,
    const float* __restrict__ ln_g, const float* __restrict__ ln_b,
    const float* __restrict__ lnc_g, const float* __restrict__ lnc_b,
    float* __restrict__ h_next, float* __restrict__ c_next_out)
{
    const int b   = blockIdx.x;
    const int tid = threadIdx.x;
    const int lane = tid & 31, warp = tid >> 5;
    const float* __restrict__ row = &g_ifgo[(size_t)b * NOUT];

    __shared__ float s_wa[8], s_wb[8];
    __shared__ float s_mean[4], s_rstd[4];
    __shared__ float s_c[HID];
    __shared__ float s_o[HID];
    __shared__ float s_cmu, s_crstd;

    #pragma unroll 1
    for (int g = 0; g < 4; ++g) {
        float sum = 0.f, sq = 0.f;
        #pragma unroll
        for (int j = tid; j < HID; j += 256) {
            float v = row[g * HID + j];
            sum += v; sq += v * v;
        }
        warpReduce2(sum, sq);
        if (lane == 0) { s_wa[warp] = sum; s_wb[warp] = sq; }
        __syncthreads();
        if (warp == 0) {
            float a2 = (lane < 8) ? s_wa[lane] : 0.f;
            float b2 = (lane < 8) ? s_wb[lane] : 0.f;
            warpReduce2(a2, b2);
            if (lane == 0) {
                float mu  = a2 * (1.0f / HID);
                float var = b2 * (1.0f / HID) - mu * mu;
                s_mean[g] = mu;
                s_rstd[g] = rsqrtf(var + 1e-5f);
            }
        }
        __syncthreads();
    }

    const float mu_i = s_mean[0], rs_i = s_rstd[0];
    const float mu_f = s_mean[1], rs_f = s_rstd[1];
    const float mu_g = s_mean[2], rs_g = s_rstd[2];
    const float mu_o = s_mean[3], rs_o = s_rstd[3];

    float csum = 0.f, csq = 0.f;
    #pragma unroll
    for (int j = tid; j < HID; j += 256) {
        float iv = (row[0 * HID + j] - mu_i) * rs_i * ln_g[0 * HID + j] + ln_b[0 * HID + j];
        float fv = (row[1 * HID + j] - mu_f) * rs_f * ln_g[1 * HID + j] + ln_b[1 * HID + j];
        float gv = (row[2 * HID + j] - mu_g) * rs_g * ln_g[2 * HID + j] + ln_b[2 * HID + j];
        float ov = (row[3 * HID + j] - mu_o) * rs_o * ln_g[3 * HID + j] + ln_b[3 * HID + j];

        float cn = sigmoidf_(fv) * c[(size_t)b * HID + j] + sigmoidf_(iv) * tanhf(gv);
        s_c[j] = cn;
        s_o[j] = ov;
        c_next_out[(size_t)b * HID + j] = cn;
        csum += cn; csq += cn * cn;
    }

    warpReduce2(csum, csq);
    if (lane == 0) { s_wa[warp] = csum; s_wb[warp] = csq; }
    __syncthreads();
    if (warp == 0) {
        float a2 = (lane < 8) ? s_wa[lane] : 0.f;
        float b2 = (lane < 8) ? s_wb[lane] : 0.f;
        warpReduce2(a2, b2);
        if (lane == 0) {
            float mu  = a2 * (1.0f / HID);
            float var = b2 * (1.0f / HID) - mu * mu;
            s_cmu = mu;
            s_crstd = rsqrtf(var + 1e-5f);
        }
    }
    __syncthreads();

    const float cmu = s_cmu, crstd = s_crstd;
    #pragma unroll
    for (int j = tid; j < HID; j += 256) {
        float lnc = (s_c[j] - cmu) * crstd * lnc_g[j] + lnc_b[j];
        h_next[(size_t)b * HID + j] = sigmoidf_(s_o[j]) * tanhf(lnc);
    }
}

// ---------------------------------------------------------------------------
extern "C" void kernel_launch(void* const* d_in, const int* in_sizes, int n_in,
                              void* d_out, int out_size)
{
    const float* x     = (const float*)d_in[0];
    const float* h     = (const float*)d_in[1];
    const float* c     = (const float*)d_in[2];
    const float* W_h   = (const float*)d_in[3];
    const float* b_h   = (const float*)d_in[4];
    const float* W_x   = (const float*)d_in[5];
    const float* ln_g  = (const float*)d_in[6];
    const float* ln_b  = (const float*)d_in[7];
    const float* lnc_g = (const float*)d_in[8];
    const float* lnc_b = (const float*)d_in[9];

    float* out    = (float*)d_out;
    float* h_next = out;
    float* c_next = out + (size_t)BATCH * HID;

    float *d_hr, *d_xr, *d_Whr, *d_Wxr;
    cudaGetSymbolAddress((void**)&d_hr,  g_hr);
    cudaGetSymbolAddress((void**)&d_xr,  g_xr);
    cudaGetSymbolAddress((void**)&d_Whr, g_Whr);
    cudaGetSymbolAddress((void**)&d_Wxr, g_Wxr);

    const int n4 = BATCH * HID;  // all four arrays are 4M elements
    cvt_tf32_kernel<<<1024, 256>>>(h, d_hr, x, d_xr, W_h, d_Whr, W_x, d_Wxr, n4);

    dim3 grid(NOUT / BN, BATCH / BM);
    gemm_tf32_kernel<<<grid, 128>>>(b_h);

    ln_lstm_kernel<<<BATCH, 256>>>(c, ln_g, ln_b, lnc_g, lnc_b, h_next, c_next);
}